// round 3
// baseline (speedup 1.0000x reference)
#include <cuda_runtime.h>
#include <math.h>

#define OBS_DIM 256
#define ACT_DIM 64
#define T_TOT   22
#define HID     32
#define MAXW    15
#define NSTEP   15
#define NGATE   96
#define KDIM    320
#define MAXB    8192

// GRU pre-activation scratch: GI[(b*15+t)*96 + g]
__device__ float g_GI[(size_t)MAXB * NSTEP * NGATE];

// ---------- packed f32x2 helpers ----------
__device__ __forceinline__ unsigned long long pk2(float lo, float hi) {
    unsigned long long r;
    asm("mov.b64 %0, {%1, %2};" : "=l"(r) : "f"(lo), "f"(hi));
    return r;
}
__device__ __forceinline__ void upk2(unsigned long long v, float& lo, float& hi) {
    asm("mov.b64 {%0, %1}, %2;" : "=f"(lo), "=f"(hi) : "l"(v));
}
__device__ __forceinline__ unsigned long long ffma2(unsigned long long a,
                                                    unsigned long long b,
                                                    unsigned long long c) {
    unsigned long long d;
    asm("fma.rn.f32x2 %0, %1, %2, %3;" : "=l"(d) : "l"(a), "l"(b), "l"(c));
    return d;
}

__device__ __forceinline__ float wsum(float x) {
#pragma unroll
    for (int o = 16; o; o >>= 1) x += __shfl_xor_sync(0xffffffffu, x, o);
    return x;
}
__device__ __forceinline__ float wmax(float x) {
#pragma unroll
    for (int o = 16; o; o >>= 1) x = fmaxf(x, __shfl_xor_sync(0xffffffffu, x, o));
    return x;
}
__device__ __forceinline__ float sigm(float x) { return 1.f / (1.f + __expf(-x)); }
__device__ __forceinline__ float tanh_fast(float x) {
    float e = __expf(-2.f * fabsf(x));
    float r = (1.f - e) / (1.f + e);
    return copysignf(r, x);
}

// =====================================================================
// Kernel 1: GI = X @ W_ih^T + b_ih   (M=B*15, N=96, K=320)
// 128 threads, 8m x 12n register tile, BK=64, dynamic smem (~59KB)
// =====================================================================
#define BM 128
#define BK 64
#define XS_STRIDE 65
#define WS_STRIDE 100

__global__ __launch_bounds__(128, 3) void k_gemm(
    const float* __restrict__ obs, const float* __restrict__ act,
    const float* __restrict__ Wih, const float* __restrict__ bih, int Bn)
{
    extern __shared__ float smem[];
    float* Xs = smem;                         // [BM][65]
    float* Ws = smem + BM * XS_STRIDE;        // [BK][100]

    const int Mtot = Bn * NSTEP;
    const int tid = threadIdx.x;
    const int tx = tid & 7, ty = tid >> 3;
    const int m_base = blockIdx.x * BM;
    const int lk4 = tid & 15;                 // float4 slot within 64-k tile
    const int lmx = tid >> 4;                 // 0..7

    const int n0 = tx * 12, m0 = ty * 8;

    unsigned long long acc[8][6];
#pragma unroll
    for (int i = 0; i < 8; i++)
#pragma unroll
        for (int p = 0; p < 6; p++) acc[i][p] = 0ULL;

#pragma unroll
    for (int kt = 0; kt < KDIM; kt += BK) {
        // --- load X tile (128 x 64): 16 passes of 8 rows ---
#pragma unroll
        for (int pass = 0; pass < 16; pass++) {
            int m  = lmx + 8 * pass;
            int gm = m_base + m;
            int gmc = gm < Mtot ? gm : Mtot - 1;
            int bb = gmc / NSTEP;
            int tt = gmc - bb * NSTEP;
            int k0 = kt + 4 * lk4;
            float4 v;
            if (kt < OBS_DIM)
                v = *(const float4*)(obs + ((size_t)(bb * T_TOT + tt)) * OBS_DIM + k0);
            else
                v = *(const float4*)(act + ((size_t)(bb * T_TOT + tt)) * ACT_DIM + (k0 - OBS_DIM));
            float* xr = Xs + m * XS_STRIDE + 4 * lk4;
            xr[0] = v.x; xr[1] = v.y; xr[2] = v.z; xr[3] = v.w;
        }
        // --- load W tile (64k x 96n) transposed to [k][n]: 12 passes of 8 rows ---
#pragma unroll
        for (int pass = 0; pass < 12; pass++) {
            int n = lmx + 8 * pass;
            float4 v = *(const float4*)(Wih + (size_t)n * KDIM + kt + 4 * lk4);
            Ws[(4 * lk4 + 0) * WS_STRIDE + n] = v.x;
            Ws[(4 * lk4 + 1) * WS_STRIDE + n] = v.y;
            Ws[(4 * lk4 + 2) * WS_STRIDE + n] = v.z;
            Ws[(4 * lk4 + 3) * WS_STRIDE + n] = v.w;
        }
        __syncthreads();

#pragma unroll 8
        for (int k = 0; k < BK; k++) {
            const float* wrow = Ws + k * WS_STRIDE + n0;
            float4 wa = *(const float4*)(wrow);
            float4 wb = *(const float4*)(wrow + 4);
            float4 wc = *(const float4*)(wrow + 8);
            unsigned long long w0 = pk2(wa.x, wa.y);
            unsigned long long w1 = pk2(wa.z, wa.w);
            unsigned long long w2 = pk2(wb.x, wb.y);
            unsigned long long w3 = pk2(wb.z, wb.w);
            unsigned long long w4 = pk2(wc.x, wc.y);
            unsigned long long w5 = pk2(wc.z, wc.w);
#pragma unroll
            for (int i = 0; i < 8; i++) {
                float x = Xs[(m0 + i) * XS_STRIDE + k];
                unsigned long long xx = pk2(x, x);
                acc[i][0] = ffma2(xx, w0, acc[i][0]);
                acc[i][1] = ffma2(xx, w1, acc[i][1]);
                acc[i][2] = ffma2(xx, w2, acc[i][2]);
                acc[i][3] = ffma2(xx, w3, acc[i][3]);
                acc[i][4] = ffma2(xx, w4, acc[i][4]);
                acc[i][5] = ffma2(xx, w5, acc[i][5]);
            }
        }
        __syncthreads();
    }

    float4 bv0 = *(const float4*)(bih + n0);
    float4 bv1 = *(const float4*)(bih + n0 + 4);
    float4 bv2 = *(const float4*)(bih + n0 + 8);

#pragma unroll
    for (int i = 0; i < 8; i++) {
        int gm = m_base + m0 + i;
        if (gm >= Mtot) continue;
        float f[12];
#pragma unroll
        for (int p = 0; p < 6; p++) upk2(acc[i][p], f[2 * p], f[2 * p + 1]);
        float4 o0 = make_float4(f[0] + bv0.x, f[1] + bv0.y, f[2] + bv0.z, f[3] + bv0.w);
        float4 o1 = make_float4(f[4] + bv1.x, f[5] + bv1.y, f[6] + bv1.z, f[7] + bv1.w);
        float4 o2 = make_float4(f[8] + bv2.x, f[9] + bv2.y, f[10] + bv2.z, f[11] + bv2.w);
        float* dst = g_GI + (size_t)gm * NGATE + n0;
        *(float4*)(dst + 0) = o0;
        *(float4*)(dst + 4) = o1;
        *(float4*)(dst + 8) = o2;
    }
}

// =====================================================================
// Kernel 2 (fused): GRU + features + LN + MLP + argmax + mask +
//                   padded-window writer. One warp per batch element.
// =====================================================================
__global__ __launch_bounds__(256) void k_fused(
    const float* __restrict__ obs, const float* __restrict__ act,
    const float* __restrict__ Whh, const float* __restrict__ bhh,
    const float* __restrict__ lng, const float* __restrict__ lnb,
    const float* __restrict__ W1, const float* __restrict__ b1,
    const float* __restrict__ W2, const float* __restrict__ b2,
    const float* __restrict__ W3, const float* __restrict__ b3,
    float* __restrict__ out, int Bn)
{
    __shared__ float w1s[64 * 35];
    __shared__ float w2s[32 * 65];
    __shared__ float w3s[14 * 33];
    __shared__ float b1s[64], b2s[32], b3s[14];
    __shared__ float gms[35], bts[35];
    __shared__ float wbuf[8][144];

    const int tid = threadIdx.x;
    for (int i = tid; i < 64 * 35; i += 256) w1s[i] = W1[i];
    for (int i = tid; i < 32 * 64; i += 256) w2s[(i >> 6) * 65 + (i & 63)] = W2[i];
    for (int i = tid; i < 14 * 32; i += 256) w3s[(i >> 5) * 33 + (i & 31)] = W3[i];
    if (tid < 64) b1s[tid] = b1[tid];
    if (tid < 32) b2s[tid] = b2[tid];
    if (tid < 14) b3s[tid] = b3[tid];
    if (tid < 35) { gms[tid] = lng[tid]; bts[tid] = lnb[tid]; }
    __syncthreads();

    const int warp = tid >> 5, j = tid & 31;
    const int b = blockIdx.x * 8 + warp;
    if (b >= Bn) return;

    // ---- GRU: W_hh rows (j, 32+j, 64+j) in registers ----
    float wr[HID], wz[HID], wn[HID];
#pragma unroll
    for (int q = 0; q < 8; q++) {
        float4 v = ((const float4*)(Whh + (size_t)j * HID))[q];
        wr[4 * q] = v.x; wr[4 * q + 1] = v.y; wr[4 * q + 2] = v.z; wr[4 * q + 3] = v.w;
    }
#pragma unroll
    for (int q = 0; q < 8; q++) {
        float4 v = ((const float4*)(Whh + (size_t)(32 + j) * HID))[q];
        wz[4 * q] = v.x; wz[4 * q + 1] = v.y; wz[4 * q + 2] = v.z; wz[4 * q + 3] = v.w;
    }
#pragma unroll
    for (int q = 0; q < 8; q++) {
        float4 v = ((const float4*)(Whh + (size_t)(64 + j) * HID))[q];
        wn[4 * q] = v.x; wn[4 * q + 1] = v.y; wn[4 * q + 2] = v.z; wn[4 * q + 3] = v.w;
    }
    const float bhr = bhh[j], bhz = bhh[32 + j], bhn = bhh[64 + j];

    const float* gip = g_GI + (size_t)b * NSTEP * NGATE;
    float gr = gip[j], gz = gip[32 + j], gn = gip[64 + j];
    float h = 0.f;

#pragma unroll 1
    for (int t = 0; t < NSTEP; t++) {
        float ngr = 0.f, ngz = 0.f, ngn = 0.f;
        if (t + 1 < NSTEP) {
            const float* q = gip + (size_t)(t + 1) * NGATE;
            ngr = q[j]; ngz = q[32 + j]; ngn = q[64 + j];
        }
        float ar = bhr, az = bhz, an = bhn;
#pragma unroll
        for (int k = 0; k < HID; k++) {
            float hk = __shfl_sync(0xffffffffu, h, k);
            ar = fmaf(wr[k], hk, ar);
            az = fmaf(wz[k], hk, az);
            an = fmaf(wn[k], hk, an);
        }
        float r = sigm(gr + ar);
        float z = sigm(gz + az);
        float n = tanh_fast(gn + r * an);
        h = (1.f - z) * n + z * h;
        gr = ngr; gz = ngz; gn = ngn;
    }

    // ---- features ----
    const float* op = obs + (size_t)b * T_TOT * OBS_DIM;
    float o11[8], o12[8], o13[8], o14[8];
#pragma unroll
    for (int i = 0; i < 8; i++) {
        o11[i] = op[11 * OBS_DIM + i * 32 + j];
        o12[i] = op[12 * OBS_DIM + i * 32 + j];
        o13[i] = op[13 * OBS_DIM + i * 32 + j];
        o14[i] = op[14 * OBS_DIM + i * 32 + j];
    }

    // entropy of softmax(obs_t)
    float mx = o14[0];
#pragma unroll
    for (int i = 1; i < 8; i++) mx = fmaxf(mx, o14[i]);
    mx = wmax(mx);
    float s = 0.f;
#pragma unroll
    for (int i = 0; i < 8; i++) s += __expf(o14[i] - mx);
    s = wsum(s);
    float inv_s = 1.f / s;
    float es = 0.f;
#pragma unroll
    for (int i = 0; i < 8; i++) {
        float p = __expf(o14[i] - mx) * inv_s;
        es += p * __logf(p + 1e-8f);
    }
    es = wsum(es);
    float entropy = -es;

    // rate of change
    float d2a = 0.f, d2b = 0.f, d2c = 0.f;
#pragma unroll
    for (int i = 0; i < 8; i++) {
        float da = o12[i] - o11[i]; d2a = fmaf(da, da, d2a);
        float db = o13[i] - o12[i]; d2b = fmaf(db, db, d2b);
        float dc = o14[i] - o13[i]; d2c = fmaf(dc, dc, d2c);
    }
    d2a = wsum(d2a); d2b = wsum(d2b); d2c = wsum(d2c);
    float roc = (sqrtf(d2a) + sqrtf(d2b) + sqrtf(d2c)) * (1.f / 3.f);

    // correlation
    float osum = 0.f;
#pragma unroll
    for (int i = 0; i < 8; i++) osum += o14[i];
    osum = wsum(osum);
    float om = osum * (1.f / 256.f);
    const float* ap = act + ((size_t)b * T_TOT + 13) * ACT_DIM;
    float a0 = ap[j], a1 = ap[32 + j];
    float am = wsum(a0 + a1) * (1.f / 256.f);
    float num = 0.f, do2 = 0.f;
#pragma unroll
    for (int i = 0; i < 8; i++) {
        float oc = o14[i] - om;
        do2 = fmaf(oc, oc, do2);
        float acv = ((i == 0) ? a0 : (i == 1) ? a1 : 0.f) - am;
        num = fmaf(oc, acv, num);
    }
    float da2 = (a0 - am) * (a0 - am) + (a1 - am) * (a1 - am) + 6.f * am * am;
    num = wsum(num); do2 = wsum(do2); da2 = wsum(da2);
    float corr = num / (sqrtf(do2) * sqrtf(da2) + 1e-8f);

    // ---- layernorm + MLP ----
    float* fb = wbuf[warp];
    if (j == 0) { fb[0] = entropy; fb[1] = roc; fb[2] = corr; }
    fb[3 + j] = h;
    __syncwarp();

    float v1 = fb[j];
    float v2 = (j < 3) ? fb[32 + j] : 0.f;
    float mu = wsum(v1 + v2) * (1.f / 35.f);
    float dd1 = v1 - mu;
    float dd2 = (j < 3) ? (v2 - mu) : 0.f;
    float var = wsum(dd1 * dd1 + dd2 * dd2) * (1.f / 35.f);
    float scl = rsqrtf(var + 1e-5f);
    __syncwarp();
    fb[j] = dd1 * scl * gms[j] + bts[j];
    if (j < 3) fb[32 + j] = dd2 * scl * gms[32 + j] + bts[32 + j];
    __syncwarp();

    float* fx1 = fb + 40;
    {
        float acc0 = b1s[j], acc1 = b1s[32 + j];
#pragma unroll
        for (int k = 0; k < 35; k++) {
            float f = fb[k];
            acc0 = fmaf(w1s[j * 35 + k], f, acc0);
            acc1 = fmaf(w1s[(32 + j) * 35 + k], f, acc1);
        }
        fx1[j] = fmaxf(acc0, 0.f);
        fx1[32 + j] = fmaxf(acc1, 0.f);
    }
    __syncwarp();

    float* fx2 = fb + 104;
    {
        float acc = b2s[j];
#pragma unroll
        for (int k = 0; k < 64; k++) acc = fmaf(w2s[j * 65 + k], fx1[k], acc);
        fx2[j] = fmaxf(acc, 0.f);
    }
    __syncwarp();

    float val = -INFINITY;
    if (j < 14) {
        float acc = b3s[j];
#pragma unroll
        for (int k = 0; k < 32; k++) acc = fmaf(w3s[j * 33 + k], fx2[k], acc);
        val = acc;
    }
    int idx = j;
#pragma unroll
    for (int off = 16; off; off >>= 1) {
        float ov = __shfl_down_sync(0xffffffffu, val, off);
        int oi = __shfl_down_sync(0xffffffffu, idx, off);
        if (ov > val || (ov == val && oi < idx)) { val = ov; idx = oi; }
    }
    idx = __shfl_sync(0xffffffffu, idx, 0);

    int wl = idx + 2;
    int s_off = (wl - 1) >> 1;
    int e_off = wl >> 1;

    // window_len
    if (j == 0) out[b] = (float)wl;
    // mask (tail region)
    if (j < MAXW) {
        int offp = j - 7;
        float mval = (offp >= -s_off && offp <= e_off) ? 1.f : 0.f;
        out[(size_t)Bn + (size_t)Bn * MAXW * KDIM + (size_t)b * MAXW + j] = mval;
    }

    // ---- padded window (fused; warp writes its own 15 rows) ----
    float* pw = out + Bn;
    const float4 z4 = make_float4(0.f, 0.f, 0.f, 0.f);
#pragma unroll 1
    for (int o = 0; o < MAXW; o++) {
        int offp = o - 7;
        bool on = (offp >= -s_off) && (offp <= e_off);
        float4* dst = (float4*)(pw + ((size_t)b * MAXW + o) * KDIM);
        if (on) {
            const float4* so = (const float4*)(obs + (size_t)(b * T_TOT + 7 + o) * OBS_DIM);
            const float4* sa = (const float4*)(act + (size_t)(b * T_TOT + 7 + o) * ACT_DIM);
            float4 v0 = so[j];
            float4 v1 = so[32 + j];
            dst[j] = v0;
            dst[32 + j] = v1;
            if (j < 16) dst[64 + j] = sa[j];
        } else {
            dst[j] = z4;
            dst[32 + j] = z4;
            if (j < 16) dst[64 + j] = z4;
        }
    }
}

// =====================================================================
extern "C" void kernel_launch(void* const* d_in, const int* in_sizes, int n_in,
                              void* d_out, int out_size)
{
    const float* obs = (const float*)d_in[0];
    const float* act = (const float*)d_in[1];
    const float* Wih = (const float*)d_in[2];
    const float* Whh = (const float*)d_in[3];
    const float* bih = (const float*)d_in[4];
    const float* bhh = (const float*)d_in[5];
    const float* lng = (const float*)d_in[6];
    const float* lnb = (const float*)d_in[7];
    const float* W1  = (const float*)d_in[8];
    const float* b1  = (const float*)d_in[9];
    const float* W2  = (const float*)d_in[10];
    const float* b2  = (const float*)d_in[11];
    const float* W3  = (const float*)d_in[12];
    const float* b3  = (const float*)d_in[13];

    int Bn = in_sizes[0] / (T_TOT * OBS_DIM);
    if (Bn > MAXB) Bn = MAXB;
    float* out = (float*)d_out;

    const int smem_bytes = (BM * XS_STRIDE + BK * WS_STRIDE) * sizeof(float);
    static bool attr_set = false;
    if (!attr_set) {
        cudaFuncSetAttribute(k_gemm, cudaFuncAttributeMaxDynamicSharedMemorySize, smem_bytes);
        attr_set = true;
    }

    int Mtot = Bn * NSTEP;
    int gemm_blocks = (Mtot + BM - 1) / BM;
    k_gemm<<<gemm_blocks, 128, smem_bytes>>>(obs, act, Wih, bih, Bn);

    int gru_blocks = (Bn + 7) / 8;
    k_fused<<<gru_blocks, 256>>>(obs, act, Whh, bhh, lng, lnb,
                                 W1, b1, W2, b2, W3, b3, out, Bn);
}

// round 4
// speedup vs baseline: 1.0163x; 1.0163x over previous
#include <cuda_runtime.h>
#include <math.h>

#define OBS_DIM 256
#define ACT_DIM 64
#define T_TOT   22
#define HID     32
#define MAXW    15
#define NSTEP   15
#define NGATE   96
#define KDIM    320
#define MAXB    8192
#define NCHUNK  4

// GRU pre-activation scratch: GI[(b*15+t)*96 + g]
__device__ float g_GI[(size_t)MAXB * NSTEP * NGATE];

// ---------- packed f32x2 helpers ----------
__device__ __forceinline__ unsigned long long pk2(float lo, float hi) {
    unsigned long long r;
    asm("mov.b64 %0, {%1, %2};" : "=l"(r) : "f"(lo), "f"(hi));
    return r;
}
__device__ __forceinline__ void upk2(unsigned long long v, float& lo, float& hi) {
    asm("mov.b64 {%0, %1}, %2;" : "=f"(lo), "=f"(hi) : "l"(v));
}
__device__ __forceinline__ unsigned long long ffma2(unsigned long long a,
                                                    unsigned long long b,
                                                    unsigned long long c) {
    unsigned long long d;
    asm("fma.rn.f32x2 %0, %1, %2, %3;" : "=l"(d) : "l"(a), "l"(b), "l"(c));
    return d;
}

__device__ __forceinline__ float wsum(float x) {
#pragma unroll
    for (int o = 16; o; o >>= 1) x += __shfl_xor_sync(0xffffffffu, x, o);
    return x;
}
__device__ __forceinline__ float wmax(float x) {
#pragma unroll
    for (int o = 16; o; o >>= 1) x = fmaxf(x, __shfl_xor_sync(0xffffffffu, x, o));
    return x;
}
__device__ __forceinline__ float sigm(float x) { return 1.f / (1.f + __expf(-x)); }
__device__ __forceinline__ float tanh_fast(float x) {
    float e = __expf(-2.f * fabsf(x));
    float r = (1.f - e) / (1.f + e);
    return copysignf(r, x);
}

// =====================================================================
// Kernel 1 (R2 known-good): GI = X @ W_ih^T + b_ih, chunked by batch.
// 128 threads, 8m x 12n register tile, BK=32, static smem.
// b0 = first batch element of this chunk, Bc = chunk batch count.
// =====================================================================
#define BM 128
#define BK 32

__global__ __launch_bounds__(128, 3) void k_gemm(
    const float* __restrict__ obs, const float* __restrict__ act,
    const float* __restrict__ Wih, const float* __restrict__ bih,
    int b0, int Bc)
{
    __shared__ __align__(16) float Xs[BM][33];
    __shared__ __align__(16) float Ws[BK][100];

    const int Mtot = Bc * NSTEP;                 // rows in this chunk
    const int tid = threadIdx.x;
    const int tx = tid & 7, ty = tid >> 3;
    const int m_base = blockIdx.x * BM;
    const int lm  = tid >> 3;                    // 0..15
    const int lk4 = tid & 7;

    const int n0 = tx * 12, m0 = ty * 8;

    unsigned long long acc[8][6];
#pragma unroll
    for (int i = 0; i < 8; i++)
#pragma unroll
        for (int p = 0; p < 6; p++) acc[i][p] = 0ULL;

    for (int kt = 0; kt < KDIM; kt += BK) {
#pragma unroll
        for (int pass = 0; pass < 8; pass++) {
            int m  = lm + 16 * pass;
            int gm = m_base + m;
            int gmc = gm < Mtot ? gm : Mtot - 1;
            int bb = b0 + gmc / NSTEP;
            int tt = gmc % NSTEP;
            int k0 = kt + 4 * lk4;
            float4 v;
            if (kt < OBS_DIM)
                v = *(const float4*)(obs + ((size_t)(bb * T_TOT + tt)) * OBS_DIM + k0);
            else
                v = *(const float4*)(act + ((size_t)(bb * T_TOT + tt)) * ACT_DIM + (k0 - OBS_DIM));
            Xs[m][4 * lk4 + 0] = v.x;
            Xs[m][4 * lk4 + 1] = v.y;
            Xs[m][4 * lk4 + 2] = v.z;
            Xs[m][4 * lk4 + 3] = v.w;
        }
#pragma unroll
        for (int pass = 0; pass < 6; pass++) {
            int n = lm + 16 * pass;
            float4 v = *(const float4*)(Wih + (size_t)n * KDIM + kt + 4 * lk4);
            Ws[4 * lk4 + 0][n] = v.x;
            Ws[4 * lk4 + 1][n] = v.y;
            Ws[4 * lk4 + 2][n] = v.z;
            Ws[4 * lk4 + 3][n] = v.w;
        }
        __syncthreads();

#pragma unroll 8
        for (int k = 0; k < BK; k++) {
            float4 wa = *(const float4*)&Ws[k][n0];
            float4 wb = *(const float4*)&Ws[k][n0 + 4];
            float4 wc = *(const float4*)&Ws[k][n0 + 8];
            unsigned long long w0 = pk2(wa.x, wa.y);
            unsigned long long w1 = pk2(wa.z, wa.w);
            unsigned long long w2 = pk2(wb.x, wb.y);
            unsigned long long w3 = pk2(wb.z, wb.w);
            unsigned long long w4 = pk2(wc.x, wc.y);
            unsigned long long w5 = pk2(wc.z, wc.w);
#pragma unroll
            for (int i = 0; i < 8; i++) {
                float x = Xs[m0 + i][k];
                unsigned long long xx = pk2(x, x);
                acc[i][0] = ffma2(xx, w0, acc[i][0]);
                acc[i][1] = ffma2(xx, w1, acc[i][1]);
                acc[i][2] = ffma2(xx, w2, acc[i][2]);
                acc[i][3] = ffma2(xx, w3, acc[i][3]);
                acc[i][4] = ffma2(xx, w4, acc[i][4]);
                acc[i][5] = ffma2(xx, w5, acc[i][5]);
            }
        }
        __syncthreads();
    }

    float4 bv0 = *(const float4*)(bih + n0);
    float4 bv1 = *(const float4*)(bih + n0 + 4);
    float4 bv2 = *(const float4*)(bih + n0 + 8);

#pragma unroll
    for (int i = 0; i < 8; i++) {
        int gm = m_base + m0 + i;
        if (gm >= Mtot) continue;
        float f[12];
#pragma unroll
        for (int p = 0; p < 6; p++) upk2(acc[i][p], f[2 * p], f[2 * p + 1]);
        float4 o0 = make_float4(f[0] + bv0.x, f[1] + bv0.y, f[2] + bv0.z, f[3] + bv0.w);
        float4 o1 = make_float4(f[4] + bv1.x, f[5] + bv1.y, f[6] + bv1.z, f[7] + bv1.w);
        float4 o2 = make_float4(f[8] + bv2.x, f[9] + bv2.y, f[10] + bv2.z, f[11] + bv2.w);
        float* dst = g_GI + ((size_t)b0 * NSTEP + gm) * NGATE + n0;
        *(float4*)(dst + 0) = o0;
        *(float4*)(dst + 4) = o1;
        *(float4*)(dst + 8) = o2;
    }
}

// =====================================================================
// Kernel 2 (fused): GRU + features + LN + MLP + argmax + mask + window,
// chunked: handles batches [b0, b0+Bc). Bn = total batch for layout.
// =====================================================================
__global__ __launch_bounds__(256) void k_fused(
    const float* __restrict__ obs, const float* __restrict__ act,
    const float* __restrict__ Whh, const float* __restrict__ bhh,
    const float* __restrict__ lng, const float* __restrict__ lnb,
    const float* __restrict__ W1, const float* __restrict__ b1,
    const float* __restrict__ W2, const float* __restrict__ b2,
    const float* __restrict__ W3, const float* __restrict__ b3,
    float* __restrict__ out, int b0, int Bc, int Bn)
{
    __shared__ float w1s[64 * 35];
    __shared__ float w2s[32 * 65];
    __shared__ float w3s[14 * 33];
    __shared__ float b1s[64], b2s[32], b3s[14];
    __shared__ float gms[35], bts[35];
    __shared__ float wbuf[8][144];

    const int tid = threadIdx.x;
    for (int i = tid; i < 64 * 35; i += 256) w1s[i] = W1[i];
    for (int i = tid; i < 32 * 64; i += 256) w2s[(i >> 6) * 65 + (i & 63)] = W2[i];
    for (int i = tid; i < 14 * 32; i += 256) w3s[(i >> 5) * 33 + (i & 31)] = W3[i];
    if (tid < 64) b1s[tid] = b1[tid];
    if (tid < 32) b2s[tid] = b2[tid];
    if (tid < 14) b3s[tid] = b3[tid];
    if (tid < 35) { gms[tid] = lng[tid]; bts[tid] = lnb[tid]; }
    __syncthreads();

    const int warp = tid >> 5, j = tid & 31;
    const int b = b0 + blockIdx.x * 8 + warp;
    if (b >= b0 + Bc) return;

    float wr[HID], wz[HID], wn[HID];
#pragma unroll
    for (int q = 0; q < 8; q++) {
        float4 v = ((const float4*)(Whh + (size_t)j * HID))[q];
        wr[4 * q] = v.x; wr[4 * q + 1] = v.y; wr[4 * q + 2] = v.z; wr[4 * q + 3] = v.w;
    }
#pragma unroll
    for (int q = 0; q < 8; q++) {
        float4 v = ((const float4*)(Whh + (size_t)(32 + j) * HID))[q];
        wz[4 * q] = v.x; wz[4 * q + 1] = v.y; wz[4 * q + 2] = v.z; wz[4 * q + 3] = v.w;
    }
#pragma unroll
    for (int q = 0; q < 8; q++) {
        float4 v = ((const float4*)(Whh + (size_t)(64 + j) * HID))[q];
        wn[4 * q] = v.x; wn[4 * q + 1] = v.y; wn[4 * q + 2] = v.z; wn[4 * q + 3] = v.w;
    }
    const float bhr = bhh[j], bhz = bhh[32 + j], bhn = bhh[64 + j];

    const float* gip = g_GI + (size_t)b * NSTEP * NGATE;
    float gr = gip[j], gz = gip[32 + j], gn = gip[64 + j];
    float h = 0.f;

#pragma unroll 1
    for (int t = 0; t < NSTEP; t++) {
        float ngr = 0.f, ngz = 0.f, ngn = 0.f;
        if (t + 1 < NSTEP) {
            const float* q = gip + (size_t)(t + 1) * NGATE;
            ngr = q[j]; ngz = q[32 + j]; ngn = q[64 + j];
        }
        float ar = bhr, az = bhz, an = bhn;
#pragma unroll
        for (int k = 0; k < HID; k++) {
            float hk = __shfl_sync(0xffffffffu, h, k);
            ar = fmaf(wr[k], hk, ar);
            az = fmaf(wz[k], hk, az);
            an = fmaf(wn[k], hk, an);
        }
        float r = sigm(gr + ar);
        float z = sigm(gz + az);
        float n = tanh_fast(gn + r * an);
        h = (1.f - z) * n + z * h;
        gr = ngr; gz = ngz; gn = ngn;
    }

    const float* op = obs + (size_t)b * T_TOT * OBS_DIM;
    float o11[8], o12[8], o13[8], o14[8];
#pragma unroll
    for (int i = 0; i < 8; i++) {
        o11[i] = op[11 * OBS_DIM + i * 32 + j];
        o12[i] = op[12 * OBS_DIM + i * 32 + j];
        o13[i] = op[13 * OBS_DIM + i * 32 + j];
        o14[i] = op[14 * OBS_DIM + i * 32 + j];
    }

    float mx = o14[0];
#pragma unroll
    for (int i = 1; i < 8; i++) mx = fmaxf(mx, o14[i]);
    mx = wmax(mx);
    float s = 0.f;
#pragma unroll
    for (int i = 0; i < 8; i++) s += __expf(o14[i] - mx);
    s = wsum(s);
    float inv_s = 1.f / s;
    float es = 0.f;
#pragma unroll
    for (int i = 0; i < 8; i++) {
        float p = __expf(o14[i] - mx) * inv_s;
        es += p * __logf(p + 1e-8f);
    }
    es = wsum(es);
    float entropy = -es;

    float d2a = 0.f, d2b = 0.f, d2c = 0.f;
#pragma unroll
    for (int i = 0; i < 8; i++) {
        float da = o12[i] - o11[i]; d2a = fmaf(da, da, d2a);
        float db = o13[i] - o12[i]; d2b = fmaf(db, db, d2b);
        float dc = o14[i] - o13[i]; d2c = fmaf(dc, dc, d2c);
    }
    d2a = wsum(d2a); d2b = wsum(d2b); d2c = wsum(d2c);
    float roc = (sqrtf(d2a) + sqrtf(d2b) + sqrtf(d2c)) * (1.f / 3.f);

    float osum = 0.f;
#pragma unroll
    for (int i = 0; i < 8; i++) osum += o14[i];
    osum = wsum(osum);
    float om = osum * (1.f / 256.f);
    const float* ap = act + ((size_t)b * T_TOT + 13) * ACT_DIM;
    float a0 = ap[j], a1 = ap[32 + j];
    float am = wsum(a0 + a1) * (1.f / 256.f);
    float num = 0.f, do2 = 0.f;
#pragma unroll
    for (int i = 0; i < 8; i++) {
        float oc = o14[i] - om;
        do2 = fmaf(oc, oc, do2);
        float acv = ((i == 0) ? a0 : (i == 1) ? a1 : 0.f) - am;
        num = fmaf(oc, acv, num);
    }
    float da2 = (a0 - am) * (a0 - am) + (a1 - am) * (a1 - am) + 6.f * am * am;
    num = wsum(num); do2 = wsum(do2); da2 = wsum(da2);
    float corr = num / (sqrtf(do2) * sqrtf(da2) + 1e-8f);

    float* fb = wbuf[warp];
    if (j == 0) { fb[0] = entropy; fb[1] = roc; fb[2] = corr; }
    fb[3 + j] = h;
    __syncwarp();

    float v1 = fb[j];
    float v2 = (j < 3) ? fb[32 + j] : 0.f;
    float mu = wsum(v1 + v2) * (1.f / 35.f);
    float dd1 = v1 - mu;
    float dd2 = (j < 3) ? (v2 - mu) : 0.f;
    float var = wsum(dd1 * dd1 + dd2 * dd2) * (1.f / 35.f);
    float scl = rsqrtf(var + 1e-5f);
    __syncwarp();
    fb[j] = dd1 * scl * gms[j] + bts[j];
    if (j < 3) fb[32 + j] = dd2 * scl * gms[32 + j] + bts[32 + j];
    __syncwarp();

    float* fx1 = fb + 40;
    {
        float acc0 = b1s[j], acc1 = b1s[32 + j];
#pragma unroll
        for (int k = 0; k < 35; k++) {
            float f = fb[k];
            acc0 = fmaf(w1s[j * 35 + k], f, acc0);
            acc1 = fmaf(w1s[(32 + j) * 35 + k], f, acc1);
        }
        fx1[j] = fmaxf(acc0, 0.f);
        fx1[32 + j] = fmaxf(acc1, 0.f);
    }
    __syncwarp();

    float* fx2 = fb + 104;
    {
        float acc = b2s[j];
#pragma unroll
        for (int k = 0; k < 64; k++) acc = fmaf(w2s[j * 65 + k], fx1[k], acc);
        fx2[j] = fmaxf(acc, 0.f);
    }
    __syncwarp();

    float val = -INFINITY;
    if (j < 14) {
        float acc = b3s[j];
#pragma unroll
        for (int k = 0; k < 32; k++) acc = fmaf(w3s[j * 33 + k], fx2[k], acc);
        val = acc;
    }
    int idx = j;
#pragma unroll
    for (int off = 16; off; off >>= 1) {
        float ov = __shfl_down_sync(0xffffffffu, val, off);
        int oi = __shfl_down_sync(0xffffffffu, idx, off);
        if (ov > val || (ov == val && oi < idx)) { val = ov; idx = oi; }
    }
    idx = __shfl_sync(0xffffffffu, idx, 0);

    int wl = idx + 2;
    int s_off = (wl - 1) >> 1;
    int e_off = wl >> 1;

    if (j == 0) out[b] = (float)wl;
    if (j < MAXW) {
        int offp = j - 7;
        float mval = (offp >= -s_off && offp <= e_off) ? 1.f : 0.f;
        out[(size_t)Bn + (size_t)Bn * MAXW * KDIM + (size_t)b * MAXW + j] = mval;
    }

    float* pw = out + Bn;
    const float4 z4 = make_float4(0.f, 0.f, 0.f, 0.f);
#pragma unroll 1
    for (int o = 0; o < MAXW; o++) {
        int offp = o - 7;
        bool on = (offp >= -s_off) && (offp <= e_off);
        float4* dst = (float4*)(pw + ((size_t)b * MAXW + o) * KDIM);
        if (on) {
            const float4* so = (const float4*)(obs + (size_t)(b * T_TOT + 7 + o) * OBS_DIM);
            const float4* sa = (const float4*)(act + (size_t)(b * T_TOT + 7 + o) * ACT_DIM);
            float4 v0 = so[j];
            float4 v1 = so[32 + j];
            dst[j] = v0;
            dst[32 + j] = v1;
            if (j < 16) dst[64 + j] = sa[j];
        } else {
            dst[j] = z4;
            dst[32 + j] = z4;
            if (j < 16) dst[64 + j] = z4;
        }
    }
}

// =====================================================================
extern "C" void kernel_launch(void* const* d_in, const int* in_sizes, int n_in,
                              void* d_out, int out_size)
{
    const float* obs = (const float*)d_in[0];
    const float* act = (const float*)d_in[1];
    const float* Wih = (const float*)d_in[2];
    const float* Whh = (const float*)d_in[3];
    const float* bih = (const float*)d_in[4];
    const float* bhh = (const float*)d_in[5];
    const float* lng = (const float*)d_in[6];
    const float* lnb = (const float*)d_in[7];
    const float* W1  = (const float*)d_in[8];
    const float* b1  = (const float*)d_in[9];
    const float* W2  = (const float*)d_in[10];
    const float* b2  = (const float*)d_in[11];
    const float* W3  = (const float*)d_in[12];
    const float* b3  = (const float*)d_in[13];

    int Bn = in_sizes[0] / (T_TOT * OBS_DIM);
    if (Bn > MAXB) Bn = MAXB;
    float* out = (float*)d_out;

    // one-time stream/event setup (first call = correctness run, not captured)
    static cudaStream_t s1 = nullptr;
    static cudaEvent_t eg[NCHUNK];
    static cudaEvent_t ef_last = nullptr;
    if (!s1) {
        cudaStreamCreateWithFlags(&s1, cudaStreamNonBlocking);
        for (int c = 0; c < NCHUNK; c++)
            cudaEventCreateWithFlags(&eg[c], cudaEventDisableTiming);
        cudaEventCreateWithFlags(&ef_last, cudaEventDisableTiming);
    }

    // chunk boundaries (batch elements)
    int cb[NCHUNK + 1];
    for (int c = 0; c <= NCHUNK; c++) cb[c] = (int)(((long long)Bn * c) / NCHUNK);

    // GEMM chunks on the main (capture) stream, each followed by an event
    for (int c = 0; c < NCHUNK; c++) {
        int b0 = cb[c], Bc = cb[c + 1] - cb[c];
        if (Bc <= 0) { cudaEventRecord(eg[c], 0); continue; }
        int gemm_blocks = (Bc * NSTEP + BM - 1) / BM;
        k_gemm<<<gemm_blocks, 128, 0, 0>>>(obs, act, Wih, bih, b0, Bc);
        cudaEventRecord(eg[c], 0);
    }

    // fused chunks on the side stream, gated per-chunk
    for (int c = 0; c < NCHUNK; c++) {
        int b0 = cb[c], Bc = cb[c + 1] - cb[c];
        cudaStreamWaitEvent(s1, eg[c], 0);
        if (Bc <= 0) continue;
        int fused_blocks = (Bc + 7) / 8;
        k_fused<<<fused_blocks, 256, 0, s1>>>(obs, act, Whh, bhh, lng, lnb,
                                              W1, b1, W2, b2, W3, b3,
                                              out, b0, Bc, Bn);
    }

    // join the fork back into the main stream
    cudaEventRecord(ef_last, s1);
    cudaStreamWaitEvent(0, ef_last, 0);
}

// round 6
// speedup vs baseline: 1.0797x; 1.0624x over previous
#include <cuda_runtime.h>
#include <math.h>
#include <stdint.h>

#define OBS_DIM 256
#define ACT_DIM 64
#define T_TOT   22
#define HID     32
#define MAXW    15
#define NSTEP   15
#define NGATE   96
#define KDIM    320
#define MAXB    8192

// GRU pre-activation scratch: GI[(b*15+t)*96 + g]
__device__ float g_GI[(size_t)MAXB * NSTEP * NGATE];
// W_ih transposed to k-major [320][96]
__device__ __align__(16) float g_Wt[KDIM * NGATE];

// ---------- packed f32x2 helpers ----------
__device__ __forceinline__ unsigned long long pk2(float lo, float hi) {
    unsigned long long r;
    asm("mov.b64 %0, {%1, %2};" : "=l"(r) : "f"(lo), "f"(hi));
    return r;
}
__device__ __forceinline__ void upk2(unsigned long long v, float& lo, float& hi) {
    asm("mov.b64 {%0, %1}, %2;" : "=f"(lo), "=f"(hi) : "l"(v));
}
__device__ __forceinline__ unsigned long long ffma2(unsigned long long a,
                                                    unsigned long long b,
                                                    unsigned long long c) {
    unsigned long long d;
    asm("fma.rn.f32x2 %0, %1, %2, %3;" : "=l"(d) : "l"(a), "l"(b), "l"(c));
    return d;
}

// ---------- cp.async helpers (sm_80 PTX, valid on compute_103) ----------
__device__ __forceinline__ void cp16(uint32_t dst, const void* src) {
    asm volatile("cp.async.ca.shared.global [%0], [%1], 16;"
                 :: "r"(dst), "l"(src) : "memory");
}
__device__ __forceinline__ void cp_commit() {
    asm volatile("cp.async.commit_group;" ::: "memory");
}
template <int N>
__device__ __forceinline__ void cp_wait() {
    asm volatile("cp.async.wait_group %0;" :: "n"(N) : "memory");
}

__device__ __forceinline__ float wsum(float x) {
#pragma unroll
    for (int o = 16; o; o >>= 1) x += __shfl_xor_sync(0xffffffffu, x, o);
    return x;
}
__device__ __forceinline__ float wmax(float x) {
#pragma unroll
    for (int o = 16; o; o >>= 1) x = fmaxf(x, __shfl_xor_sync(0xffffffffu, x, o));
    return x;
}
__device__ __forceinline__ float sigm(float x) { return 1.f / (1.f + __expf(-x)); }
__device__ __forceinline__ float tanh_fast(float x) {
    float e = __expf(-2.f * fabsf(x));
    float r = (1.f - e) / (1.f + e);
    return copysignf(r, x);
}

// =====================================================================
// Kernel 0: transpose W_ih [96][320] -> g_Wt [320][96]
// =====================================================================
__global__ void k_wprep(const float* __restrict__ Wih) {
    int i = blockIdx.x * 256 + threadIdx.x;
    if (i < KDIM * NGATE) {
        int k = i / NGATE, n = i - k * NGATE;
        g_Wt[i] = Wih[(size_t)n * KDIM + k];
    }
}

// =====================================================================
// Kernel 1: GI = X @ W_ih^T + b_ih  (M=B*15, N=96, K=320)
// cp.async double-buffered tiles; 8m x 12n register tile per thread.
// =====================================================================
#define BM 128
#define BK 32
#define XSTR 36                         // X smem row stride (floats), 144B
#define XBUF (BM * XSTR)                // 4608 floats per buffer
#define WBUF (BK * NGATE)               // 3072 floats per buffer
#define GEMM_SMEM_FLOATS (2 * XBUF + 2 * WBUF)
#define GEMM_SMEM_BYTES (GEMM_SMEM_FLOATS * 4)

__global__ __launch_bounds__(128, 3) void k_gemm(
    const float* __restrict__ obs, const float* __restrict__ act,
    const float* __restrict__ bih, int Bn)
{
    extern __shared__ float sm[];
    float* Xs = sm;                      // [2][BM][XSTR]
    float* Ws = sm + 2 * XBUF;           // [2][BK][NGATE]
    __shared__ int rowidx[BM];           // (bb*22+tt) per tile row

    const int Mtot = Bn * NSTEP;
    const int tid = threadIdx.x;
    const int tx = tid & 7, ty = tid >> 3;
    const int m_base = blockIdx.x * BM;
    const int n0 = tx * 12, m0 = ty * 8;

    // row index table (once per CTA)
    if (tid < BM) {
        int gm = m_base + tid;
        int gmc = gm < Mtot ? gm : Mtot - 1;
        int bb = gmc / NSTEP;
        int tt = gmc - bb * NSTEP;
        rowidx[tid] = bb * T_TOT + tt;
    }
    __syncthreads();

    const uint32_t xs_base = (uint32_t)__cvta_generic_to_shared(Xs);
    const uint32_t ws_base = (uint32_t)__cvta_generic_to_shared(Ws);

    // ---- tile loader via cp.async ----
    auto load_tile = [&](int pb, int kt) {
        // X tile: 128 rows x 32 floats = 1024 16B-chunks, 8 per thread
        uint32_t xb = xs_base + (uint32_t)pb * XBUF * 4;
        const bool from_obs = (kt < 8);
        const int kk = from_obs ? kt * BK : (kt - 8) * BK;
#pragma unroll
        for (int i = 0; i < 8; i++) {
            int c = i * 128 + tid;
            int r = c >> 3, piece = c & 7;
            uint32_t dst = xb + (uint32_t)(r * XSTR + piece * 4) * 4;
            const float* src = from_obs
                ? obs + (size_t)rowidx[r] * OBS_DIM + kk + piece * 4
                : act + (size_t)rowidx[r] * ACT_DIM + kk + piece * 4;
            cp16(dst, src);
        }
        // W tile: 32 k-rows x 96 floats = 768 chunks, 6 per thread
        uint32_t wb = ws_base + (uint32_t)pb * WBUF * 4;
        const float* wsrc = g_Wt + (size_t)kt * BK * NGATE;
#pragma unroll
        for (int i = 0; i < 6; i++) {
            int c = i * 128 + tid;
            int kr = c / 24, piece = c - kr * 24;
            uint32_t dst = wb + (uint32_t)(kr * NGATE + piece * 4) * 4;
            cp16(dst, wsrc + kr * NGATE + piece * 4);
        }
    };

    unsigned long long acc[8][6];
#pragma unroll
    for (int i = 0; i < 8; i++)
#pragma unroll
        for (int p = 0; p < 6; p++) acc[i][p] = 0ULL;

    load_tile(0, 0);
    cp_commit();

#pragma unroll 1
    for (int kt = 0; kt < 10; kt++) {
        const int pb = kt & 1;
        if (kt + 1 < 10) {
            load_tile((kt + 1) & 1, kt + 1);
            cp_commit();
            cp_wait<1>();
        } else {
            cp_wait<0>();
        }
        __syncthreads();

        const float* xp = Xs + pb * XBUF;
        const float* wp = Ws + pb * WBUF;
#pragma unroll 8
        for (int k = 0; k < BK; k++) {
            const float* wrow = wp + k * NGATE + n0;
            float4 wa = *(const float4*)(wrow);
            float4 wb4 = *(const float4*)(wrow + 4);
            float4 wc = *(const float4*)(wrow + 8);
            unsigned long long w0 = pk2(wa.x, wa.y);
            unsigned long long w1 = pk2(wa.z, wa.w);
            unsigned long long w2 = pk2(wb4.x, wb4.y);
            unsigned long long w3 = pk2(wb4.z, wb4.w);
            unsigned long long w4 = pk2(wc.x, wc.y);
            unsigned long long w5 = pk2(wc.z, wc.w);
#pragma unroll
            for (int i = 0; i < 8; i++) {
                float x = xp[(m0 + i) * XSTR + k];
                unsigned long long xx = pk2(x, x);
                acc[i][0] = ffma2(xx, w0, acc[i][0]);
                acc[i][1] = ffma2(xx, w1, acc[i][1]);
                acc[i][2] = ffma2(xx, w2, acc[i][2]);
                acc[i][3] = ffma2(xx, w3, acc[i][3]);
                acc[i][4] = ffma2(xx, w4, acc[i][4]);
                acc[i][5] = ffma2(xx, w5, acc[i][5]);
            }
        }
        __syncthreads();
    }

    float4 bv0 = *(const float4*)(bih + n0);
    float4 bv1 = *(const float4*)(bih + n0 + 4);
    float4 bv2 = *(const float4*)(bih + n0 + 8);

#pragma unroll
    for (int i = 0; i < 8; i++) {
        int gm = m_base + m0 + i;
        if (gm >= Mtot) continue;
        float f[12];
#pragma unroll
        for (int p = 0; p < 6; p++) upk2(acc[i][p], f[2 * p], f[2 * p + 1]);
        float4 o0 = make_float4(f[0] + bv0.x, f[1] + bv0.y, f[2] + bv0.z, f[3] + bv0.w);
        float4 o1 = make_float4(f[4] + bv1.x, f[5] + bv1.y, f[6] + bv1.z, f[7] + bv1.w);
        float4 o2 = make_float4(f[8] + bv2.x, f[9] + bv2.y, f[10] + bv2.z, f[11] + bv2.w);
        float* dst = g_GI + (size_t)gm * NGATE + n0;
        *(float4*)(dst + 0) = o0;
        *(float4*)(dst + 4) = o1;
        *(float4*)(dst + 8) = o2;
    }
}

// =====================================================================
// Kernel 2 (fused, known-good): GRU + features + LN + MLP + argmax +
// mask + padded window. One warp per batch element.
// =====================================================================
__global__ __launch_bounds__(256) void k_fused(
    const float* __restrict__ obs, const float* __restrict__ act,
    const float* __restrict__ Whh, const float* __restrict__ bhh,
    const float* __restrict__ lng, const float* __restrict__ lnb,
    const float* __restrict__ W1, const float* __restrict__ b1,
    const float* __restrict__ W2, const float* __restrict__ b2,
    const float* __restrict__ W3, const float* __restrict__ b3,
    float* __restrict__ out, int Bn)
{
    __shared__ float w1s[64 * 35];
    __shared__ float w2s[32 * 65];
    __shared__ float w3s[14 * 33];
    __shared__ float b1s[64], b2s[32], b3s[14];
    __shared__ float gms[35], bts[35];
    __shared__ float wbuf[8][144];

    const int tid = threadIdx.x;
    for (int i = tid; i < 64 * 35; i += 256) w1s[i] = W1[i];
    for (int i = tid; i < 32 * 64; i += 256) w2s[(i >> 6) * 65 + (i & 63)] = W2[i];
    for (int i = tid; i < 14 * 32; i += 256) w3s[(i >> 5) * 33 + (i & 31)] = W3[i];
    if (tid < 64) b1s[tid] = b1[tid];
    if (tid < 32) b2s[tid] = b2[tid];
    if (tid < 14) b3s[tid] = b3[tid];
    if (tid < 35) { gms[tid] = lng[tid]; bts[tid] = lnb[tid]; }
    __syncthreads();

    const int warp = tid >> 5, j = tid & 31;
    const int b = blockIdx.x * 8 + warp;
    if (b >= Bn) return;

    float wr[HID], wz[HID], wn[HID];
#pragma unroll
    for (int q = 0; q < 8; q++) {
        float4 v = ((const float4*)(Whh + (size_t)j * HID))[q];
        wr[4 * q] = v.x; wr[4 * q + 1] = v.y; wr[4 * q + 2] = v.z; wr[4 * q + 3] = v.w;
    }
#pragma unroll
    for (int q = 0; q < 8; q++) {
        float4 v = ((const float4*)(Whh + (size_t)(32 + j) * HID))[q];
        wz[4 * q] = v.x; wz[4 * q + 1] = v.y; wz[4 * q + 2] = v.z; wz[4 * q + 3] = v.w;
    }
#pragma unroll
    for (int q = 0; q < 8; q++) {
        float4 v = ((const float4*)(Whh + (size_t)(64 + j) * HID))[q];
        wn[4 * q] = v.x; wn[4 * q + 1] = v.y; wn[4 * q + 2] = v.z; wn[4 * q + 3] = v.w;
    }
    const float bhr = bhh[j], bhz = bhh[32 + j], bhn = bhh[64 + j];

    const float* gip = g_GI + (size_t)b * NSTEP * NGATE;
    float gr = gip[j], gz = gip[32 + j], gn = gip[64 + j];
    float h = 0.f;

#pragma unroll 1
    for (int t = 0; t < NSTEP; t++) {
        float ngr = 0.f, ngz = 0.f, ngn = 0.f;
        if (t + 1 < NSTEP) {
            const float* q = gip + (size_t)(t + 1) * NGATE;
            ngr = q[j]; ngz = q[32 + j]; ngn = q[64 + j];
        }
        float ar = bhr, az = bhz, an = bhn;
#pragma unroll
        for (int k = 0; k < HID; k++) {
            float hk = __shfl_sync(0xffffffffu, h, k);
            ar = fmaf(wr[k], hk, ar);
            az = fmaf(wz[k], hk, az);
            an = fmaf(wn[k], hk, an);
        }
        float r = sigm(gr + ar);
        float z = sigm(gz + az);
        float n = tanh_fast(gn + r * an);
        h = (1.f - z) * n + z * h;
        gr = ngr; gz = ngz; gn = ngn;
    }

    const float* op = obs + (size_t)b * T_TOT * OBS_DIM;
    float o11[8], o12[8], o13[8], o14[8];
#pragma unroll
    for (int i = 0; i < 8; i++) {
        o11[i] = op[11 * OBS_DIM + i * 32 + j];
        o12[i] = op[12 * OBS_DIM + i * 32 + j];
        o13[i] = op[13 * OBS_DIM + i * 32 + j];
        o14[i] = op[14 * OBS_DIM + i * 32 + j];
    }

    float mx = o14[0];
#pragma unroll
    for (int i = 1; i < 8; i++) mx = fmaxf(mx, o14[i]);
    mx = wmax(mx);
    float s = 0.f;
#pragma unroll
    for (int i = 0; i < 8; i++) s += __expf(o14[i] - mx);
    s = wsum(s);
    float inv_s = 1.f / s;
    float es = 0.f;
#pragma unroll
    for (int i = 0; i < 8; i++) {
        float p = __expf(o14[i] - mx) * inv_s;
        es += p * __logf(p + 1e-8f);
    }
    es = wsum(es);
    float entropy = -es;

    float d2a = 0.f, d2b = 0.f, d2c = 0.f;
#pragma unroll
    for (int i = 0; i < 8; i++) {
        float da = o12[i] - o11[i]; d2a = fmaf(da, da, d2a);
        float db = o13[i] - o12[i]; d2b = fmaf(db, db, d2b);
        float dc = o14[i] - o13[i]; d2c = fmaf(dc, dc, d2c);
    }
    d2a = wsum(d2a); d2b = wsum(d2b); d2c = wsum(d2c);
    float roc = (sqrtf(d2a) + sqrtf(d2b) + sqrtf(d2c)) * (1.f / 3.f);

    float osum = 0.f;
#pragma unroll
    for (int i = 0; i < 8; i++) osum += o14[i];
    osum = wsum(osum);
    float om = osum * (1.f / 256.f);
    const float* ap = act + ((size_t)b * T_TOT + 13) * ACT_DIM;
    float a0 = ap[j], a1 = ap[32 + j];
    float am = wsum(a0 + a1) * (1.f / 256.f);
    float num = 0.f, do2 = 0.f;
#pragma unroll
    for (int i = 0; i < 8; i++) {
        float oc = o14[i] - om;
        do2 = fmaf(oc, oc, do2);
        float acv = ((i == 0) ? a0 : (i == 1) ? a1 : 0.f) - am;
        num = fmaf(oc, acv, num);
    }
    float da2 = (a0 - am) * (a0 - am) + (a1 - am) * (a1 - am) + 6.f * am * am;
    num = wsum(num); do2 = wsum(do2); da2 = wsum(da2);
    float corr = num / (sqrtf(do2) * sqrtf(da2) + 1e-8f);

    float* fb = wbuf[warp];
    if (j == 0) { fb[0] = entropy; fb[1] = roc; fb[2] = corr; }
    fb[3 + j] = h;
    __syncwarp();

    float v1 = fb[j];
    float v2 = (j < 3) ? fb[32 + j] : 0.f;
    float mu = wsum(v1 + v2) * (1.f / 35.f);
    float dd1 = v1 - mu;
    float dd2 = (j < 3) ? (v2 - mu) : 0.f;
    float var = wsum(dd1 * dd1 + dd2 * dd2) * (1.f / 35.f);
    float scl = rsqrtf(var + 1e-5f);
    __syncwarp();
    fb[j] = dd1 * scl * gms[j] + bts[j];
    if (j < 3) fb[32 + j] = dd2 * scl * gms[32 + j] + bts[32 + j];
    __syncwarp();

    float* fx1 = fb + 40;
    {
        float acc0 = b1s[j], acc1 = b1s[32 + j];
#pragma unroll
        for (int k = 0; k < 35; k++) {
            float f = fb[k];
            acc0 = fmaf(w1s[j * 35 + k], f, acc0);
            acc1 = fmaf(w1s[(32 + j) * 35 + k], f, acc1);
        }
        fx1[j] = fmaxf(acc0, 0.f);
        fx1[32 + j] = fmaxf(acc1, 0.f);
    }
    __syncwarp();

    float* fx2 = fb + 104;
    {
        float acc = b2s[j];
#pragma unroll
        for (int k = 0; k < 64; k++) acc = fmaf(w2s[j * 65 + k], fx1[k], acc);
        fx2[j] = fmaxf(acc, 0.f);
    }
    __syncwarp();

    float val = -INFINITY;
    if (j < 14) {
        float acc = b3s[j];
#pragma unroll
        for (int k = 0; k < 32; k++) acc = fmaf(w3s[j * 33 + k], fx2[k], acc);
        val = acc;
    }
    int idx = j;
#pragma unroll
    for (int off = 16; off; off >>= 1) {
        float ov = __shfl_down_sync(0xffffffffu, val, off);
        int oi = __shfl_down_sync(0xffffffffu, idx, off);
        if (ov > val || (ov == val && oi < idx)) { val = ov; idx = oi; }
    }
    idx = __shfl_sync(0xffffffffu, idx, 0);

    int wl = idx + 2;
    int s_off = (wl - 1) >> 1;
    int e_off = wl >> 1;

    if (j == 0) out[b] = (float)wl;
    if (j < MAXW) {
        int offp = j - 7;
        float mval = (offp >= -s_off && offp <= e_off) ? 1.f : 0.f;
        out[(size_t)Bn + (size_t)Bn * MAXW * KDIM + (size_t)b * MAXW + j] = mval;
    }

    float* pw = out + Bn;
    const float4 z4 = make_float4(0.f, 0.f, 0.f, 0.f);
#pragma unroll 1
    for (int o = 0; o < MAXW; o++) {
        int offp = o - 7;
        bool on = (offp >= -s_off) && (offp <= e_off);
        float4* dst = (float4*)(pw + ((size_t)b * MAXW + o) * KDIM);
        if (on) {
            const float4* so = (const float4*)(obs + (size_t)(b * T_TOT + 7 + o) * OBS_DIM);
            const float4* sa = (const float4*)(act + (size_t)(b * T_TOT + 7 + o) * ACT_DIM);
            float4 v0 = so[j];
            float4 v1 = so[32 + j];
            dst[j] = v0;
            dst[32 + j] = v1;
            if (j < 16) dst[64 + j] = sa[j];
        } else {
            dst[j] = z4;
            dst[32 + j] = z4;
            if (j < 16) dst[64 + j] = z4;
        }
    }
}

// =====================================================================
extern "C" void kernel_launch(void* const* d_in, const int* in_sizes, int n_in,
                              void* d_out, int out_size)
{
    const float* obs = (const float*)d_in[0];
    const float* act = (const float*)d_in[1];
    const float* Wih = (const float*)d_in[2];
    const float* Whh = (const float*)d_in[3];
    const float* bih = (const float*)d_in[4];
    const float* bhh = (const float*)d_in[5];
    const float* lng = (const float*)d_in[6];
    const float* lnb = (const float*)d_in[7];
    const float* W1  = (const float*)d_in[8];
    const float* b1  = (const float*)d_in[9];
    const float* W2  = (const float*)d_in[10];
    const float* b2  = (const float*)d_in[11];
    const float* W3  = (const float*)d_in[12];
    const float* b3  = (const float*)d_in[13];

    int Bn = in_sizes[0] / (T_TOT * OBS_DIM);
    if (Bn > MAXB) Bn = MAXB;
    float* out = (float*)d_out;

    static bool attr_set = false;
    if (!attr_set) {
        cudaFuncSetAttribute(k_gemm, cudaFuncAttributeMaxDynamicSharedMemorySize,
                             GEMM_SMEM_BYTES);
        attr_set = true;
    }

    k_wprep<<<(KDIM * NGATE + 255) / 256, 256>>>(Wih);

    int Mtot = Bn * NSTEP;
    int gemm_blocks = (Mtot + BM - 1) / BM;
    k_gemm<<<gemm_blocks, 128, GEMM_SMEM_BYTES>>>(obs, act, bih, Bn);

    int fused_blocks = (Bn + 7) / 8;
    k_fused<<<fused_blocks, 256>>>(obs, act, Whh, bhh, lng, lnb,
                                   W1, b1, W2, b2, W3, b3, out, Bn);
}

// round 7
// speedup vs baseline: 1.1286x; 1.0453x over previous
#include <cuda_runtime.h>
#include <math.h>
#include <stdint.h>

#define OBS_DIM 256
#define ACT_DIM 64
#define T_TOT   22
#define HID     32
#define MAXW    15
#define NSTEP   15
#define NGATE   96
#define KDIM    320
#define MAXB    8192

// GRU pre-activation scratch: GI[(b*15+t)*96 + g]
__device__ float g_GI[(size_t)MAXB * NSTEP * NGATE];

// ---------- packed f32x2 helpers ----------
__device__ __forceinline__ unsigned long long pk2(float lo, float hi) {
    unsigned long long r;
    asm("mov.b64 %0, {%1, %2};" : "=l"(r) : "f"(lo), "f"(hi));
    return r;
}
__device__ __forceinline__ void upk2(unsigned long long v, float& lo, float& hi) {
    asm("mov.b64 {%0, %1}, %2;" : "=f"(lo), "=f"(hi) : "l"(v));
}
__device__ __forceinline__ unsigned long long ffma2(unsigned long long a,
                                                    unsigned long long b,
                                                    unsigned long long c) {
    unsigned long long d;
    asm("fma.rn.f32x2 %0, %1, %2, %3;" : "=l"(d) : "l"(a), "l"(b), "l"(c));
    return d;
}

__device__ __forceinline__ float wsum(float x) {
#pragma unroll
    for (int o = 16; o; o >>= 1) x += __shfl_xor_sync(0xffffffffu, x, o);
    return x;
}
__device__ __forceinline__ float wmax(float x) {
#pragma unroll
    for (int o = 16; o; o >>= 1) x = fmaxf(x, __shfl_xor_sync(0xffffffffu, x, o));
    return x;
}
__device__ __forceinline__ float sigm(float x) { return 1.f / (1.f + __expf(-x)); }
__device__ __forceinline__ float tanh_fast(float x) {
    float e = __expf(-2.f * fabsf(x));
    float r = (1.f - e) / (1.f + e);
    return copysignf(r, x);
}

// =====================================================================
// Kernel 1 (R2 known-good, 171us): GI = X @ W_ih^T + b_ih
// 128 threads: tx = tid&7 -> 12 n each, ty = tid>>3 -> 8 m each
// =====================================================================
#define BM 128
#define BK 32

__global__ __launch_bounds__(128, 3) void k_gemm(
    const float* __restrict__ obs, const float* __restrict__ act,
    const float* __restrict__ Wih, const float* __restrict__ bih, int Bn)
{
    __shared__ __align__(16) float Xs[BM][33];
    __shared__ __align__(16) float Ws[BK][100];

    const int Mtot = Bn * NSTEP;
    const int tid = threadIdx.x;
    const int tx = tid & 7, ty = tid >> 3;
    const int m_base = blockIdx.x * BM;
    const int lm  = tid >> 3;
    const int lk4 = tid & 7;

    const int n0 = tx * 12, m0 = ty * 8;

    unsigned long long acc[8][6];
#pragma unroll
    for (int i = 0; i < 8; i++)
#pragma unroll
        for (int p = 0; p < 6; p++) acc[i][p] = 0ULL;

    for (int kt = 0; kt < KDIM; kt += BK) {
#pragma unroll
        for (int pass = 0; pass < 8; pass++) {
            int m  = lm + 16 * pass;
            int gm = m_base + m;
            int gmc = gm < Mtot ? gm : Mtot - 1;
            int bb = gmc / NSTEP;
            int tt = gmc - bb * NSTEP;
            int k0 = kt + 4 * lk4;
            float4 v;
            if (kt < OBS_DIM)
                v = *(const float4*)(obs + ((size_t)(bb * T_TOT + tt)) * OBS_DIM + k0);
            else
                v = *(const float4*)(act + ((size_t)(bb * T_TOT + tt)) * ACT_DIM + (k0 - OBS_DIM));
            Xs[m][4 * lk4 + 0] = v.x;
            Xs[m][4 * lk4 + 1] = v.y;
            Xs[m][4 * lk4 + 2] = v.z;
            Xs[m][4 * lk4 + 3] = v.w;
        }
#pragma unroll
        for (int pass = 0; pass < 6; pass++) {
            int n = lm + 16 * pass;
            float4 v = *(const float4*)(Wih + (size_t)n * KDIM + kt + 4 * lk4);
            Ws[4 * lk4 + 0][n] = v.x;
            Ws[4 * lk4 + 1][n] = v.y;
            Ws[4 * lk4 + 2][n] = v.z;
            Ws[4 * lk4 + 3][n] = v.w;
        }
        __syncthreads();

#pragma unroll 8
        for (int k = 0; k < BK; k++) {
            float4 wa = *(const float4*)&Ws[k][n0];
            float4 wb = *(const float4*)&Ws[k][n0 + 4];
            float4 wc = *(const float4*)&Ws[k][n0 + 8];
            unsigned long long w0 = pk2(wa.x, wa.y);
            unsigned long long w1 = pk2(wa.z, wa.w);
            unsigned long long w2 = pk2(wb.x, wb.y);
            unsigned long long w3 = pk2(wb.z, wb.w);
            unsigned long long w4 = pk2(wc.x, wc.y);
            unsigned long long w5 = pk2(wc.z, wc.w);
#pragma unroll
            for (int i = 0; i < 8; i++) {
                float x = Xs[m0 + i][k];
                unsigned long long xx = pk2(x, x);
                acc[i][0] = ffma2(xx, w0, acc[i][0]);
                acc[i][1] = ffma2(xx, w1, acc[i][1]);
                acc[i][2] = ffma2(xx, w2, acc[i][2]);
                acc[i][3] = ffma2(xx, w3, acc[i][3]);
                acc[i][4] = ffma2(xx, w4, acc[i][4]);
                acc[i][5] = ffma2(xx, w5, acc[i][5]);
            }
        }
        __syncthreads();
    }

    float4 bv0 = *(const float4*)(bih + n0);
    float4 bv1 = *(const float4*)(bih + n0 + 4);
    float4 bv2 = *(const float4*)(bih + n0 + 8);

#pragma unroll
    for (int i = 0; i < 8; i++) {
        int gm = m_base + m0 + i;
        if (gm >= Mtot) continue;
        float f[12];
#pragma unroll
        for (int p = 0; p < 6; p++) upk2(acc[i][p], f[2 * p], f[2 * p + 1]);
        float4 o0 = make_float4(f[0] + bv0.x, f[1] + bv0.y, f[2] + bv0.z, f[3] + bv0.w);
        float4 o1 = make_float4(f[4] + bv1.x, f[5] + bv1.y, f[6] + bv1.z, f[7] + bv1.w);
        float4 o2 = make_float4(f[8] + bv2.x, f[9] + bv2.y, f[10] + bv2.z, f[11] + bv2.w);
        float* dst = g_GI + (size_t)gm * NGATE + n0;
        *(float4*)(dst + 0) = o0;
        *(float4*)(dst + 4) = o1;
        *(float4*)(dst + 8) = o2;
    }
}

// =====================================================================
// Kernel 2 (fused, latency-optimized): GRU (smem h broadcast, split
// accumulators) + features + LN + MLP + argmax + mask + grouped window.
// One warp per batch element.
// =====================================================================
__global__ __launch_bounds__(256) void k_fused(
    const float* __restrict__ obs, const float* __restrict__ act,
    const float* __restrict__ Whh, const float* __restrict__ bhh,
    const float* __restrict__ lng, const float* __restrict__ lnb,
    const float* __restrict__ W1, const float* __restrict__ b1,
    const float* __restrict__ W2, const float* __restrict__ b2,
    const float* __restrict__ W3, const float* __restrict__ b3,
    float* __restrict__ out, int Bn)
{
    __shared__ float w1s[64 * 35];
    __shared__ float w2s[32 * 65];
    __shared__ float w3s[14 * 33];
    __shared__ float b1s[64], b2s[32], b3s[14];
    __shared__ float gms[35], bts[35];
    __shared__ float wbuf[8][144];
    __shared__ float hs[8][32];          // per-warp h broadcast buffer

    const int tid = threadIdx.x;
    for (int i = tid; i < 64 * 35; i += 256) w1s[i] = W1[i];
    for (int i = tid; i < 32 * 64; i += 256) w2s[(i >> 6) * 65 + (i & 63)] = W2[i];
    for (int i = tid; i < 14 * 32; i += 256) w3s[(i >> 5) * 33 + (i & 31)] = W3[i];
    if (tid < 64) b1s[tid] = b1[tid];
    if (tid < 32) b2s[tid] = b2[tid];
    if (tid < 14) b3s[tid] = b3[tid];
    if (tid < 35) { gms[tid] = lng[tid]; bts[tid] = lnb[tid]; }
    __syncthreads();

    const int warp = tid >> 5, j = tid & 31;
    const int b = blockIdx.x * 8 + warp;
    if (b >= Bn) return;

    // ---- GRU weights: rows (j, 32+j, 64+j) in registers ----
    float wr[HID], wz[HID], wn[HID];
#pragma unroll
    for (int q = 0; q < 8; q++) {
        float4 v = ((const float4*)(Whh + (size_t)j * HID))[q];
        wr[4 * q] = v.x; wr[4 * q + 1] = v.y; wr[4 * q + 2] = v.z; wr[4 * q + 3] = v.w;
    }
#pragma unroll
    for (int q = 0; q < 8; q++) {
        float4 v = ((const float4*)(Whh + (size_t)(32 + j) * HID))[q];
        wz[4 * q] = v.x; wz[4 * q + 1] = v.y; wz[4 * q + 2] = v.z; wz[4 * q + 3] = v.w;
    }
#pragma unroll
    for (int q = 0; q < 8; q++) {
        float4 v = ((const float4*)(Whh + (size_t)(64 + j) * HID))[q];
        wn[4 * q] = v.x; wn[4 * q + 1] = v.y; wn[4 * q + 2] = v.z; wn[4 * q + 3] = v.w;
    }
    const float bhr = bhh[j], bhz = bhh[32 + j], bhn = bhh[64 + j];

    const float* gip = g_GI + (size_t)b * NSTEP * NGATE;
    float gr = gip[j], gz = gip[32 + j], gn = gip[64 + j];
    float h = 0.f;
    float* myh = hs[warp];

#pragma unroll 1
    for (int t = 0; t < NSTEP; t++) {
        float ngr = 0.f, ngz = 0.f, ngn = 0.f;
        if (t + 1 < NSTEP) {
            const float* q = gip + (size_t)(t + 1) * NGATE;
            ngr = q[j]; ngz = q[32 + j]; ngn = q[64 + j];
        }
        myh[j] = h;
        __syncwarp();
        // 6 independent chains of depth 16 (2 accumulators per gate)
        float ar0 = 0.f, az0 = 0.f, an0 = 0.f;
        float ar1 = 0.f, az1 = 0.f, an1 = 0.f;
#pragma unroll
        for (int k = 0; k < 16; k++) {
            float h0 = myh[k];
            float h1 = myh[16 + k];
            ar0 = fmaf(wr[k], h0, ar0);
            az0 = fmaf(wz[k], h0, az0);
            an0 = fmaf(wn[k], h0, an0);
            ar1 = fmaf(wr[16 + k], h1, ar1);
            az1 = fmaf(wz[16 + k], h1, az1);
            an1 = fmaf(wn[16 + k], h1, an1);
        }
        float ar = bhr + ar0 + ar1;
        float az = bhz + az0 + az1;
        float an = bhn + an0 + an1;
        float r = sigm(gr + ar);
        float z = sigm(gz + az);
        float n = tanh_fast(gn + r * an);
        __syncwarp();
        h = (1.f - z) * n + z * h;
        gr = ngr; gz = ngz; gn = ngn;
    }

    // ---- features ----
    const float* op = obs + (size_t)b * T_TOT * OBS_DIM;
    float o11[8], o12[8], o13[8], o14[8];
#pragma unroll
    for (int i = 0; i < 8; i++) {
        o11[i] = op[11 * OBS_DIM + i * 32 + j];
        o12[i] = op[12 * OBS_DIM + i * 32 + j];
        o13[i] = op[13 * OBS_DIM + i * 32 + j];
        o14[i] = op[14 * OBS_DIM + i * 32 + j];
    }

    float mx = o14[0];
#pragma unroll
    for (int i = 1; i < 8; i++) mx = fmaxf(mx, o14[i]);
    mx = wmax(mx);
    float s = 0.f;
#pragma unroll
    for (int i = 0; i < 8; i++) s += __expf(o14[i] - mx);
    s = wsum(s);
    float inv_s = 1.f / s;
    float es = 0.f;
#pragma unroll
    for (int i = 0; i < 8; i++) {
        float p = __expf(o14[i] - mx) * inv_s;
        es += p * __logf(p + 1e-8f);
    }
    es = wsum(es);
    float entropy = -es;

    float d2a = 0.f, d2b = 0.f, d2c = 0.f;
#pragma unroll
    for (int i = 0; i < 8; i++) {
        float da = o12[i] - o11[i]; d2a = fmaf(da, da, d2a);
        float db = o13[i] - o12[i]; d2b = fmaf(db, db, d2b);
        float dc = o14[i] - o13[i]; d2c = fmaf(dc, dc, d2c);
    }
    d2a = wsum(d2a); d2b = wsum(d2b); d2c = wsum(d2c);
    float roc = (sqrtf(d2a) + sqrtf(d2b) + sqrtf(d2c)) * (1.f / 3.f);

    float osum = 0.f;
#pragma unroll
    for (int i = 0; i < 8; i++) osum += o14[i];
    osum = wsum(osum);
    float om = osum * (1.f / 256.f);
    const float* ap = act + ((size_t)b * T_TOT + 13) * ACT_DIM;
    float a0 = ap[j], a1 = ap[32 + j];
    float am = wsum(a0 + a1) * (1.f / 256.f);
    float num = 0.f, do2 = 0.f;
#pragma unroll
    for (int i = 0; i < 8; i++) {
        float oc = o14[i] - om;
        do2 = fmaf(oc, oc, do2);
        float acv = ((i == 0) ? a0 : (i == 1) ? a1 : 0.f) - am;
        num = fmaf(oc, acv, num);
    }
    float da2 = (a0 - am) * (a0 - am) + (a1 - am) * (a1 - am) + 6.f * am * am;
    num = wsum(num); do2 = wsum(do2); da2 = wsum(da2);
    float corr = num / (sqrtf(do2) * sqrtf(da2) + 1e-8f);

    // ---- layernorm + MLP ----
    float* fb = wbuf[warp];
    if (j == 0) { fb[0] = entropy; fb[1] = roc; fb[2] = corr; }
    fb[3 + j] = h;
    __syncwarp();

    float v1 = fb[j];
    float v2 = (j < 3) ? fb[32 + j] : 0.f;
    float mu = wsum(v1 + v2) * (1.f / 35.f);
    float dd1 = v1 - mu;
    float dd2 = (j < 3) ? (v2 - mu) : 0.f;
    float var = wsum(dd1 * dd1 + dd2 * dd2) * (1.f / 35.f);
    float scl = rsqrtf(var + 1e-5f);
    __syncwarp();
    fb[j] = dd1 * scl * gms[j] + bts[j];
    if (j < 3) fb[32 + j] = dd2 * scl * gms[32 + j] + bts[32 + j];
    __syncwarp();

    float* fx1 = fb + 40;
    {
        float acc0 = b1s[j], acc1 = b1s[32 + j];
#pragma unroll
        for (int k = 0; k < 35; k++) {
            float f = fb[k];
            acc0 = fmaf(w1s[j * 35 + k], f, acc0);
            acc1 = fmaf(w1s[(32 + j) * 35 + k], f, acc1);
        }
        fx1[j] = fmaxf(acc0, 0.f);
        fx1[32 + j] = fmaxf(acc1, 0.f);
    }
    __syncwarp();

    float* fx2 = fb + 104;
    {
        float acc = b2s[j];
#pragma unroll
        for (int k = 0; k < 64; k++) acc = fmaf(w2s[j * 65 + k], fx1[k], acc);
        fx2[j] = fmaxf(acc, 0.f);
    }
    __syncwarp();

    float val = -INFINITY;
    if (j < 14) {
        float acc = b3s[j];
#pragma unroll
        for (int k = 0; k < 32; k++) acc = fmaf(w3s[j * 33 + k], fx2[k], acc);
        val = acc;
    }
    int idx = j;
#pragma unroll
    for (int off = 16; off; off >>= 1) {
        float ov = __shfl_down_sync(0xffffffffu, val, off);
        int oi = __shfl_down_sync(0xffffffffu, idx, off);
        if (ov > val || (ov == val && oi < idx)) { val = ov; idx = oi; }
    }
    idx = __shfl_sync(0xffffffffu, idx, 0);

    int wl = idx + 2;
    int s_off = (wl - 1) >> 1;
    int e_off = wl >> 1;

    if (j == 0) out[b] = (float)wl;
    if (j < MAXW) {
        int offp = j - 7;
        float mval = (offp >= -s_off && offp <= e_off) ? 1.f : 0.f;
        out[(size_t)Bn + (size_t)Bn * MAXW * KDIM + (size_t)b * MAXW + j] = mval;
    }

    // ---- padded window: 3 groups of 5 rows; loads batched before stores ----
    float* pw = out + Bn;
    const float4 z4 = make_float4(0.f, 0.f, 0.f, 0.f);
    const int lo_row = 7 - s_off, hi_row = 7 + e_off;
#pragma unroll
    for (int g = 0; g < 3; g++) {
        float4 va[5], vb[5], vc[5];
        // issue all loads for this group (independent -> MLP 10-15)
#pragma unroll
        for (int r = 0; r < 5; r++) {
            int o = g * 5 + r;
            bool on = (o >= lo_row) && (o <= hi_row);
            if (on) {
                const float4* so = (const float4*)(obs + (size_t)(b * T_TOT + 7 + o) * OBS_DIM);
                va[r] = so[j];
                vb[r] = so[32 + j];
                if (j < 16) {
                    const float4* sa = (const float4*)(act + (size_t)(b * T_TOT + 7 + o) * ACT_DIM);
                    vc[r] = sa[j];
                } else vc[r] = z4;
            } else {
                va[r] = z4; vb[r] = z4; vc[r] = z4;
            }
        }
        // stores
#pragma unroll
        for (int r = 0; r < 5; r++) {
            int o = g * 5 + r;
            float4* dst = (float4*)(pw + ((size_t)b * MAXW + o) * KDIM);
            dst[j] = va[r];
            dst[32 + j] = vb[r];
            if (j < 16) dst[64 + j] = vc[r];
        }
    }
}

// =====================================================================
extern "C" void kernel_launch(void* const* d_in, const int* in_sizes, int n_in,
                              void* d_out, int out_size)
{
    const float* obs = (const float*)d_in[0];
    const float* act = (const float*)d_in[1];
    const float* Wih = (const float*)d_in[2];
    const float* Whh = (const float*)d_in[3];
    const float* bih = (const float*)d_in[4];
    const float* bhh = (const float*)d_in[5];
    const float* lng = (const float*)d_in[6];
    const float* lnb = (const float*)d_in[7];
    const float* W1  = (const float*)d_in[8];
    const float* b1  = (const float*)d_in[9];
    const float* W2  = (const float*)d_in[10];
    const float* b2  = (const float*)d_in[11];
    const float* W3  = (const float*)d_in[12];
    const float* b3  = (const float*)d_in[13];

    int Bn = in_sizes[0] / (T_TOT * OBS_DIM);
    if (Bn > MAXB) Bn = MAXB;
    float* out = (float*)d_out;

    int Mtot = Bn * NSTEP;
    int gemm_blocks = (Mtot + BM - 1) / BM;
    k_gemm<<<gemm_blocks, 128>>>(obs, act, Wih, bih, Bn);

    int fused_blocks = (Bn + 7) / 8;
    k_fused<<<fused_blocks, 256>>>(obs, act, Whh, bhh, lng, lnb,
                                   W1, b1, W2, b2, W3, b3, out, Bn);
}

// round 8
// speedup vs baseline: 1.2069x; 1.0694x over previous
#include <cuda_runtime.h>
#include <math.h>
#include <stdint.h>

#define OBS_DIM 256
#define ACT_DIM 64
#define T_TOT   22
#define HID     32
#define MAXW    15
#define NSTEP   15
#define NGATE   96
#define KDIM    320
#define MAXB    8192

// GRU pre-activation scratch: GI[(b*15+t)*96 + g]
__device__ float g_GI[(size_t)MAXB * NSTEP * NGATE];

// ---------- packed f32x2 helpers ----------
__device__ __forceinline__ unsigned long long pk2(float lo, float hi) {
    unsigned long long r;
    asm("mov.b64 %0, {%1, %2};" : "=l"(r) : "f"(lo), "f"(hi));
    return r;
}
__device__ __forceinline__ void upk2(unsigned long long v, float& lo, float& hi) {
    asm("mov.b64 {%0, %1}, %2;" : "=f"(lo), "=f"(hi) : "l"(v));
}
__device__ __forceinline__ unsigned long long ffma2(unsigned long long a,
                                                    unsigned long long b,
                                                    unsigned long long c) {
    unsigned long long d;
    asm("fma.rn.f32x2 %0, %1, %2, %3;" : "=l"(d) : "l"(a), "l"(b), "l"(c));
    return d;
}

__device__ __forceinline__ float wsum(float x) {
#pragma unroll
    for (int o = 16; o; o >>= 1) x += __shfl_xor_sync(0xffffffffu, x, o);
    return x;
}
__device__ __forceinline__ float wmax(float x) {
#pragma unroll
    for (int o = 16; o; o >>= 1) x = fmaxf(x, __shfl_xor_sync(0xffffffffu, x, o));
    return x;
}
__device__ __forceinline__ float sigm(float x) { return 1.f / (1.f + __expf(-x)); }
__device__ __forceinline__ float tanh_fast(float x) {
    float e = __expf(-2.f * fabsf(x));
    float r = (1.f - e) / (1.f + e);
    return copysignf(r, x);
}

// =====================================================================
// Kernel 1 (R2 known-good, 171us): GI = X @ W_ih^T + b_ih
// =====================================================================
#define BM 128
#define BK 32

__global__ __launch_bounds__(128, 3) void k_gemm(
    const float* __restrict__ obs, const float* __restrict__ act,
    const float* __restrict__ Wih, const float* __restrict__ bih, int Bn)
{
    __shared__ __align__(16) float Xs[BM][33];
    __shared__ __align__(16) float Ws[BK][100];

    const int Mtot = Bn * NSTEP;
    const int tid = threadIdx.x;
    const int tx = tid & 7, ty = tid >> 3;
    const int m_base = blockIdx.x * BM;
    const int lm  = tid >> 3;
    const int lk4 = tid & 7;

    const int n0 = tx * 12, m0 = ty * 8;

    unsigned long long acc[8][6];
#pragma unroll
    for (int i = 0; i < 8; i++)
#pragma unroll
        for (int p = 0; p < 6; p++) acc[i][p] = 0ULL;

    for (int kt = 0; kt < KDIM; kt += BK) {
#pragma unroll
        for (int pass = 0; pass < 8; pass++) {
            int m  = lm + 16 * pass;
            int gm = m_base + m;
            int gmc = gm < Mtot ? gm : Mtot - 1;
            int bb = gmc / NSTEP;
            int tt = gmc - bb * NSTEP;
            int k0 = kt + 4 * lk4;
            float4 v;
            if (kt < OBS_DIM)
                v = *(const float4*)(obs + ((size_t)(bb * T_TOT + tt)) * OBS_DIM + k0);
            else
                v = *(const float4*)(act + ((size_t)(bb * T_TOT + tt)) * ACT_DIM + (k0 - OBS_DIM));
            Xs[m][4 * lk4 + 0] = v.x;
            Xs[m][4 * lk4 + 1] = v.y;
            Xs[m][4 * lk4 + 2] = v.z;
            Xs[m][4 * lk4 + 3] = v.w;
        }
#pragma unroll
        for (int pass = 0; pass < 6; pass++) {
            int n = lm + 16 * pass;
            float4 v = *(const float4*)(Wih + (size_t)n * KDIM + kt + 4 * lk4);
            Ws[4 * lk4 + 0][n] = v.x;
            Ws[4 * lk4 + 1][n] = v.y;
            Ws[4 * lk4 + 2][n] = v.z;
            Ws[4 * lk4 + 3][n] = v.w;
        }
        __syncthreads();

#pragma unroll 8
        for (int k = 0; k < BK; k++) {
            float4 wa = *(const float4*)&Ws[k][n0];
            float4 wb = *(const float4*)&Ws[k][n0 + 4];
            float4 wc = *(const float4*)&Ws[k][n0 + 8];
            unsigned long long w0 = pk2(wa.x, wa.y);
            unsigned long long w1 = pk2(wa.z, wa.w);
            unsigned long long w2 = pk2(wb.x, wb.y);
            unsigned long long w3 = pk2(wb.z, wb.w);
            unsigned long long w4 = pk2(wc.x, wc.y);
            unsigned long long w5 = pk2(wc.z, wc.w);
#pragma unroll
            for (int i = 0; i < 8; i++) {
                float x = Xs[m0 + i][k];
                unsigned long long xx = pk2(x, x);
                acc[i][0] = ffma2(xx, w0, acc[i][0]);
                acc[i][1] = ffma2(xx, w1, acc[i][1]);
                acc[i][2] = ffma2(xx, w2, acc[i][2]);
                acc[i][3] = ffma2(xx, w3, acc[i][3]);
                acc[i][4] = ffma2(xx, w4, acc[i][4]);
                acc[i][5] = ffma2(xx, w5, acc[i][5]);
            }
        }
        __syncthreads();
    }

    float4 bv0 = *(const float4*)(bih + n0);
    float4 bv1 = *(const float4*)(bih + n0 + 4);
    float4 bv2 = *(const float4*)(bih + n0 + 8);

#pragma unroll
    for (int i = 0; i < 8; i++) {
        int gm = m_base + m0 + i;
        if (gm >= Mtot) continue;
        float f[12];
#pragma unroll
        for (int p = 0; p < 6; p++) upk2(acc[i][p], f[2 * p], f[2 * p + 1]);
        float4 o0 = make_float4(f[0] + bv0.x, f[1] + bv0.y, f[2] + bv0.z, f[3] + bv0.w);
        float4 o1 = make_float4(f[4] + bv1.x, f[5] + bv1.y, f[6] + bv1.z, f[7] + bv1.w);
        float4 o2 = make_float4(f[8] + bv2.x, f[9] + bv2.y, f[10] + bv2.z, f[11] + bv2.w);
        float* dst = g_GI + (size_t)gm * NGATE + n0;
        *(float4*)(dst + 0) = o0;
        *(float4*)(dst + 4) = o1;
        *(float4*)(dst + 8) = o2;
    }
}

// =====================================================================
// Kernel 2 (fused, register-diet): features first, W_hh in smem,
// GRU + LN + MLP + argmax + mask + grouped window.
// =====================================================================
__global__ __launch_bounds__(256, 3) void k_fused(
    const float* __restrict__ obs, const float* __restrict__ act,
    const float* __restrict__ Whh, const float* __restrict__ bhh,
    const float* __restrict__ lng, const float* __restrict__ lnb,
    const float* __restrict__ W1, const float* __restrict__ b1,
    const float* __restrict__ W2, const float* __restrict__ b2,
    const float* __restrict__ W3, const float* __restrict__ b3,
    float* __restrict__ out, int Bn)
{
    __shared__ float whr[32][33], whz[32][33], whn[32][33];
    __shared__ float w1s[64 * 35];
    __shared__ float w2s[32 * 65];
    __shared__ float w3s[14 * 33];
    __shared__ float b1s[64], b2s[32], b3s[14];
    __shared__ float gms[35], bts[35];
    __shared__ float wbuf[8][144];
    __shared__ float hs[8][32];

    const int tid = threadIdx.x;
    // W_hh -> smem (shared by all warps; row j of each gate)
    for (int i = tid; i < 3 * HID * HID; i += 256) {
        int row = i >> 5, k = i & 31;
        float v = Whh[i];
        if (row < 32)       whr[row][k] = v;
        else if (row < 64)  whz[row - 32][k] = v;
        else                whn[row - 64][k] = v;
    }
    for (int i = tid; i < 64 * 35; i += 256) w1s[i] = W1[i];
    for (int i = tid; i < 32 * 64; i += 256) w2s[(i >> 6) * 65 + (i & 63)] = W2[i];
    for (int i = tid; i < 14 * 32; i += 256) w3s[(i >> 5) * 33 + (i & 31)] = W3[i];
    if (tid < 64) b1s[tid] = b1[tid];
    if (tid < 32) b2s[tid] = b2[tid];
    if (tid < 14) b3s[tid] = b3[tid];
    if (tid < 35) { gms[tid] = lng[tid]; bts[tid] = lnb[tid]; }
    __syncthreads();

    const int warp = tid >> 5, j = tid & 31;
    const int b = blockIdx.x * 8 + warp;
    if (b >= Bn) return;

    // ================= features FIRST (frees o-registers before GRU) ====
    float entropy, roc, corr;
    {
        const float* op = obs + (size_t)b * T_TOT * OBS_DIM;
        float o11[8], o12[8], o13[8], o14[8];
#pragma unroll
        for (int i = 0; i < 8; i++) {
            o11[i] = op[11 * OBS_DIM + i * 32 + j];
            o12[i] = op[12 * OBS_DIM + i * 32 + j];
            o13[i] = op[13 * OBS_DIM + i * 32 + j];
            o14[i] = op[14 * OBS_DIM + i * 32 + j];
        }

        float mx = o14[0];
#pragma unroll
        for (int i = 1; i < 8; i++) mx = fmaxf(mx, o14[i]);
        mx = wmax(mx);
        float s = 0.f;
#pragma unroll
        for (int i = 0; i < 8; i++) s += __expf(o14[i] - mx);
        s = wsum(s);
        float inv_s = 1.f / s;
        float es = 0.f;
#pragma unroll
        for (int i = 0; i < 8; i++) {
            float p = __expf(o14[i] - mx) * inv_s;
            es += p * __logf(p + 1e-8f);
        }
        es = wsum(es);
        entropy = -es;

        float d2a = 0.f, d2b = 0.f, d2c = 0.f;
#pragma unroll
        for (int i = 0; i < 8; i++) {
            float da = o12[i] - o11[i]; d2a = fmaf(da, da, d2a);
            float db = o13[i] - o12[i]; d2b = fmaf(db, db, d2b);
            float dc = o14[i] - o13[i]; d2c = fmaf(dc, dc, d2c);
        }
        d2a = wsum(d2a); d2b = wsum(d2b); d2c = wsum(d2c);
        roc = (sqrtf(d2a) + sqrtf(d2b) + sqrtf(d2c)) * (1.f / 3.f);

        float osum = 0.f;
#pragma unroll
        for (int i = 0; i < 8; i++) osum += o14[i];
        osum = wsum(osum);
        float om = osum * (1.f / 256.f);
        const float* ap = act + ((size_t)b * T_TOT + 13) * ACT_DIM;
        float a0 = ap[j], a1 = ap[32 + j];
        float am = wsum(a0 + a1) * (1.f / 256.f);
        float num = 0.f, do2 = 0.f;
#pragma unroll
        for (int i = 0; i < 8; i++) {
            float oc = o14[i] - om;
            do2 = fmaf(oc, oc, do2);
            float acv = ((i == 0) ? a0 : (i == 1) ? a1 : 0.f) - am;
            num = fmaf(oc, acv, num);
        }
        float da2 = (a0 - am) * (a0 - am) + (a1 - am) * (a1 - am) + 6.f * am * am;
        num = wsum(num); do2 = wsum(do2); da2 = wsum(da2);
        corr = num / (sqrtf(do2) * sqrtf(da2) + 1e-8f);
    }

    // ================= GRU (W_hh from smem) =============================
    const float bhr = bhh[j], bhz = bhh[32 + j], bhn = bhh[64 + j];
    const float* gip = g_GI + (size_t)b * NSTEP * NGATE;
    float gr = gip[j], gz = gip[32 + j], gn = gip[64 + j];
    float h = 0.f;
    float* myh = hs[warp];
    const float* wrj = whr[j];
    const float* wzj = whz[j];
    const float* wnj = whn[j];

#pragma unroll 1
    for (int t = 0; t < NSTEP; t++) {
        float ngr = 0.f, ngz = 0.f, ngn = 0.f;
        if (t + 1 < NSTEP) {
            const float* q = gip + (size_t)(t + 1) * NGATE;
            ngr = q[j]; ngz = q[32 + j]; ngn = q[64 + j];
        }
        myh[j] = h;
        __syncwarp();
        float ar0 = 0.f, az0 = 0.f, an0 = 0.f;
        float ar1 = 0.f, az1 = 0.f, an1 = 0.f;
#pragma unroll
        for (int k = 0; k < 16; k++) {
            float h0 = myh[k];
            float h1 = myh[16 + k];
            ar0 = fmaf(wrj[k], h0, ar0);
            az0 = fmaf(wzj[k], h0, az0);
            an0 = fmaf(wnj[k], h0, an0);
            ar1 = fmaf(wrj[16 + k], h1, ar1);
            az1 = fmaf(wzj[16 + k], h1, az1);
            an1 = fmaf(wnj[16 + k], h1, an1);
        }
        float ar = bhr + ar0 + ar1;
        float az = bhz + az0 + az1;
        float an = bhn + an0 + an1;
        float r = sigm(gr + ar);
        float z = sigm(gz + az);
        float n = tanh_fast(gn + r * an);
        __syncwarp();
        h = (1.f - z) * n + z * h;
        gr = ngr; gz = ngz; gn = ngn;
    }

    // ================= layernorm + MLP ==================================
    float* fb = wbuf[warp];
    if (j == 0) { fb[0] = entropy; fb[1] = roc; fb[2] = corr; }
    fb[3 + j] = h;
    __syncwarp();

    float v1 = fb[j];
    float v2 = (j < 3) ? fb[32 + j] : 0.f;
    float mu = wsum(v1 + v2) * (1.f / 35.f);
    float dd1 = v1 - mu;
    float dd2 = (j < 3) ? (v2 - mu) : 0.f;
    float var = wsum(dd1 * dd1 + dd2 * dd2) * (1.f / 35.f);
    float scl = rsqrtf(var + 1e-5f);
    __syncwarp();
    fb[j] = dd1 * scl * gms[j] + bts[j];
    if (j < 3) fb[32 + j] = dd2 * scl * gms[32 + j] + bts[32 + j];
    __syncwarp();

    float* fx1 = fb + 40;
    {
        float acc0 = b1s[j], acc1 = b1s[32 + j];
#pragma unroll
        for (int k = 0; k < 35; k++) {
            float f = fb[k];
            acc0 = fmaf(w1s[j * 35 + k], f, acc0);
            acc1 = fmaf(w1s[(32 + j) * 35 + k], f, acc1);
        }
        fx1[j] = fmaxf(acc0, 0.f);
        fx1[32 + j] = fmaxf(acc1, 0.f);
    }
    __syncwarp();

    float* fx2 = fb + 104;
    {
        float acc = b2s[j];
#pragma unroll
        for (int k = 0; k < 64; k++) acc = fmaf(w2s[j * 65 + k], fx1[k], acc);
        fx2[j] = fmaxf(acc, 0.f);
    }
    __syncwarp();

    float val = -INFINITY;
    if (j < 14) {
        float acc = b3s[j];
#pragma unroll
        for (int k = 0; k < 32; k++) acc = fmaf(w3s[j * 33 + k], fx2[k], acc);
        val = acc;
    }
    int idx = j;
#pragma unroll
    for (int off = 16; off; off >>= 1) {
        float ov = __shfl_down_sync(0xffffffffu, val, off);
        int oi = __shfl_down_sync(0xffffffffu, idx, off);
        if (ov > val || (ov == val && oi < idx)) { val = ov; idx = oi; }
    }
    idx = __shfl_sync(0xffffffffu, idx, 0);

    int wl = idx + 2;
    int s_off = (wl - 1) >> 1;
    int e_off = wl >> 1;

    if (j == 0) out[b] = (float)wl;
    if (j < MAXW) {
        int offp = j - 7;
        float mval = (offp >= -s_off && offp <= e_off) ? 1.f : 0.f;
        out[(size_t)Bn + (size_t)Bn * MAXW * KDIM + (size_t)b * MAXW + j] = mval;
    }

    // ---- padded window: 3 groups of 5 rows; loads batched before stores ----
    float* pw = out + Bn;
    const float4 z4 = make_float4(0.f, 0.f, 0.f, 0.f);
    const int lo_row = 7 - s_off, hi_row = 7 + e_off;
#pragma unroll
    for (int g = 0; g < 3; g++) {
        float4 va[5], vb[5], vc[5];
#pragma unroll
        for (int r = 0; r < 5; r++) {
            int o = g * 5 + r;
            bool on = (o >= lo_row) && (o <= hi_row);
            if (on) {
                const float4* so = (const float4*)(obs + (size_t)(b * T_TOT + 7 + o) * OBS_DIM);
                va[r] = so[j];
                vb[r] = so[32 + j];
                if (j < 16) {
                    const float4* sa = (const float4*)(act + (size_t)(b * T_TOT + 7 + o) * ACT_DIM);
                    vc[r] = sa[j];
                } else vc[r] = z4;
            } else {
                va[r] = z4; vb[r] = z4; vc[r] = z4;
            }
        }
#pragma unroll
        for (int r = 0; r < 5; r++) {
            int o = g * 5 + r;
            float4* dst = (float4*)(pw + ((size_t)b * MAXW + o) * KDIM);
            dst[j] = va[r];
            dst[32 + j] = vb[r];
            if (j < 16) dst[64 + j] = vc[r];
        }
    }
}

// =====================================================================
extern "C" void kernel_launch(void* const* d_in, const int* in_sizes, int n_in,
                              void* d_out, int out_size)
{
    const float* obs = (const float*)d_in[0];
    const float* act = (const float*)d_in[1];
    const float* Wih = (const float*)d_in[2];
    const float* Whh = (const float*)d_in[3];
    const float* bih = (const float*)d_in[4];
    const float* bhh = (const float*)d_in[5];
    const float* lng = (const float*)d_in[6];
    const float* lnb = (const float*)d_in[7];
    const float* W1  = (const float*)d_in[8];
    const float* b1  = (const float*)d_in[9];
    const float* W2  = (const float*)d_in[10];
    const float* b2  = (const float*)d_in[11];
    const float* W3  = (const float*)d_in[12];
    const float* b3  = (const float*)d_in[13];

    int Bn = in_sizes[0] / (T_TOT * OBS_DIM);
    if (Bn > MAXB) Bn = MAXB;
    float* out = (float*)d_out;

    int Mtot = Bn * NSTEP;
    int gemm_blocks = (Mtot + BM - 1) / BM;
    k_gemm<<<gemm_blocks, 128>>>(obs, act, Wih, bih, Bn);

    int fused_blocks = (Bn + 7) / 8;
    k_fused<<<fused_blocks, 256>>>(obs, act, Whh, bhh, lng, lnb,
                                   W1, b1, W2, b2, W3, b3, out, Bn);
}